// round 15
// baseline (speedup 1.0000x reference)
#include <cuda_runtime.h>
#include <cuda_fp16.h>
#include <cstdint>

// ---------------- problem constants ----------------
#define T_TOK 8192
#define G_GRP 8
#define K_DIM 1024
#define N_DIM 2048

// ---------------- scratch (fp16) + sync state ----------------
__device__ __half g_xh[(size_t)T_TOK * K_DIM];            // [T, 1024]  16MB
__device__ __half g_wh[(size_t)G_GRP * N_DIM * K_DIM];    // [G*N, 1024] 32MB
__device__ unsigned g_cnt[1 + G_GRP];                     // x, w0..w7 completion
__device__ unsigned g_done;                               // GEMM blocks finished

// ---------------- conversion kernel (region-ordered, flagged) ----------------
constexpr int CVB = 296;   // blocks (all resident in wave 1)
constexpr int CVT = 512;   // threads

__device__ __forceinline__ void cv8(const float* __restrict__ s,
                                    __half* __restrict__ d) {
    const float4 v0 = *reinterpret_cast<const float4*>(s);
    const float4 v1 = *reinterpret_cast<const float4*>(s + 4);
    union { __half h[8]; uint4 u; } P;
    P.h[0] = __float2half_rn(v0.x); P.h[1] = __float2half_rn(v0.y);
    P.h[2] = __float2half_rn(v0.z); P.h[3] = __float2half_rn(v0.w);
    P.h[4] = __float2half_rn(v1.x); P.h[5] = __float2half_rn(v1.y);
    P.h[6] = __float2half_rn(v1.z); P.h[7] = __float2half_rn(v1.w);
    *reinterpret_cast<uint4*>(d) = P.u;
}

__global__ __launch_bounds__(CVT)
void convert_fp16(const float* __restrict__ x, const float* __restrict__ w)
{
    // fire PDL trigger immediately: GEMM grid may begin placing now
    cudaTriggerProgrammaticLaunchCompletion();

    const size_t stride = (size_t)CVB * CVT;
    const size_t tid0 = (size_t)blockIdx.x * CVT + threadIdx.x;

    // region 0: x
    {
        const size_t X8 = (size_t)T_TOK * K_DIM / 8;
        for (size_t i = tid0; i < X8; i += stride) cv8(x + i * 8, g_xh + i * 8);
        __threadfence();
        __syncthreads();
        if (threadIdx.x == 0) atomicAdd(&g_cnt[0], 1u);
    }
    // regions 1..8: w per group, in order
    const size_t W8 = (size_t)N_DIM * K_DIM / 8;
#pragma unroll 1
    for (int g = 0; g < G_GRP; g++) {
        const float* src = w + (size_t)g * N_DIM * K_DIM;
        __half* dst = g_wh + (size_t)g * N_DIM * K_DIM;
        for (size_t i = tid0; i < W8; i += stride) cv8(src + i * 8, dst + i * 8);
        __threadfence();
        __syncthreads();
        if (threadIdx.x == 0) atomicAdd(&g_cnt[1 + g], 1u);
    }
}

// ---------------- PTX helpers (baseline features only) ----------------
__device__ __forceinline__ uint32_t smem_u32(const void* p) {
    uint32_t a;
    asm("{ .reg .u64 t; cvta.to.shared.u64 t, %1; cvt.u32.u64 %0, t; }"
        : "=r"(a) : "l"(p));
    return a;
}
__device__ __forceinline__ void cp16(uint32_t dst, const void* src) {
    asm volatile("cp.async.cg.shared.global [%0], [%1], 16;" :: "r"(dst), "l"(src));
}
#define CP_COMMIT() asm volatile("cp.async.commit_group;" ::: "memory")
#define CP_WAIT1()  asm volatile("cp.async.wait_group 1;" ::: "memory")

__device__ __forceinline__ void ldsm_x4(uint32_t& r0, uint32_t& r1,
                                        uint32_t& r2, uint32_t& r3, uint32_t a) {
    asm volatile("ldmatrix.sync.aligned.m8n8.x4.shared.b16 {%0,%1,%2,%3}, [%4];"
                 : "=r"(r0), "=r"(r1), "=r"(r2), "=r"(r3) : "r"(a));
}
__device__ __forceinline__ void mma_16816(float* c, const uint32_t* a,
                                          const uint32_t* b) {
    asm volatile(
        "mma.sync.aligned.m16n8k16.row.col.f32.f16.f16.f32 "
        "{%0,%1,%2,%3}, {%4,%5,%6,%7}, {%8,%9}, {%0,%1,%2,%3};"
        : "+f"(c[0]), "+f"(c[1]), "+f"(c[2]), "+f"(c[3])
        : "r"(a[0]), "r"(a[1]), "r"(a[2]), "r"(a[3]), "r"(b[0]), "r"(b[1]));
}
__device__ __forceinline__ unsigned ld_acq(const unsigned* p) {
    unsigned v;
    asm volatile("ld.acquire.gpu.u32 %0, [%1];" : "=r"(v) : "l"(p));
    return v;
}

// ---------------- GEMM kernel (R13 body + flag gating) ----------------
constexpr int BM = 128, BN = 128, BK = 64;
constexpr int TILE = BM * 128;                    // 16384 bytes
constexpr int STAGE_BYTES = 2 * TILE;             // 32768
constexpr int STAGES = 3;
constexpr int SMEM_TOTAL = STAGES * STAGE_BYTES;  // 98304 -> 2 CTAs/SM
constexpr int NITER = K_DIM / BK;                 // 16
constexpr int MAX_RT = T_TOK / BM + G_GRP;        // 72
constexpr unsigned GEMM_BLOCKS = (N_DIM / BN) * MAX_RT;  // 1152

__device__ __forceinline__ uint32_t swz(uint32_t row, uint32_t chunk) {
    return row * 128u + ((chunk ^ (row & 7u)) << 4);
}

__global__ __launch_bounds__(256, 2)
void grouped_gemm_hmma(const int* __restrict__ offs, float* __restrict__ out)
{
    const int tid = threadIdx.x;

    // map blockIdx.y -> (group, group-aligned row tile)
    const int rid = blockIdx.y;
    int g = -1, start = 0, hi = 0;
    {
        int a = 0;
#pragma unroll
        for (int gg = 0; gg < G_GRP; gg++) {
            const int l = gg ? __ldg(offs + gg - 1) : 0;
            const int h = __ldg(offs + gg);
            const int c = (h - l + BM - 1) >> 7;
            if (rid >= a && rid < a + c) { g = gg; start = l + ((rid - a) << 7); hi = h; }
            a += c;
        }
    }

    if (g >= 0) {
        // ---- wait until x and this group's w are converted ----
        if (tid == 0) {
            while (ld_acq(&g_cnt[0]) < (unsigned)CVB) __nanosleep(64);
            while (ld_acq(&g_cnt[1 + g]) < (unsigned)CVB) __nanosleep(64);
        }
        __syncthreads();

        const int n0 = blockIdx.x * BN;

        extern __shared__ __align__(1024) char smem[];
        const uint32_t sb = smem_u32(smem);

        const int wid  = tid >> 5;
        const int lane = tid & 31;
        const int WM0 = (wid >> 2) * 64;
        const int WN0 = (wid & 3) * 32;
        const int c8 = tid & 7;
        const int r0 = tid >> 3;

        const __half* aP[4];
        const __half* bP[4];
#pragma unroll
        for (int j = 0; j < 4; j++) {
            int r = start + r0 + 32 * j;
            if (r > T_TOK - 1) r = T_TOK - 1;
            aP[j] = g_xh + (size_t)r * K_DIM + c8 * 8;
            bP[j] = g_wh + ((size_t)g * N_DIM + n0 + r0 + 32 * j) * K_DIM + c8 * 8;
        }

        auto load_stage = [&](int s) {
            const int kb = s * BK;
            const uint32_t base = sb + (uint32_t)(s % STAGES) * STAGE_BYTES;
#pragma unroll
            for (int j = 0; j < 4; j++) {
                const uint32_t so = swz((uint32_t)r0 + 32u * j, c8);
                cp16(base + so,        aP[j] + kb);
                cp16(base + TILE + so, bP[j] + kb);
            }
        };

        float acc[4][4][4];
#pragma unroll
        for (int i = 0; i < 4; i++)
#pragma unroll
            for (int j = 0; j < 4; j++)
#pragma unroll
                for (int q = 0; q < 4; q++) acc[i][j][q] = 0.0f;

        load_stage(0); CP_COMMIT();
        load_stage(1); CP_COMMIT();

        for (int it = 0; it < NITER; it++) {
            CP_WAIT1();
            __syncthreads();

            if (it + 2 < NITER) load_stage(it + 2);
            CP_COMMIT();

            const uint32_t aT = sb + (uint32_t)(it % STAGES) * STAGE_BYTES;
            const uint32_t bT = aT + TILE;

#pragma unroll
            for (int ks = 0; ks < BK / 16; ks++) {
                const uint32_t cA = 2u * ks;
                uint32_t a[4][4], b[4][2];
#pragma unroll
                for (int i = 0; i < 4; i++) {
                    const uint32_t row = (uint32_t)(WM0 + i * 16 + (lane & 15));
                    const uint32_t ch  = cA + (uint32_t)(lane >> 4);
                    ldsm_x4(a[i][0], a[i][1], a[i][2], a[i][3], aT + swz(row, ch));
                }
#pragma unroll
                for (int jp = 0; jp < 2; jp++) {
                    const uint32_t row = (uint32_t)(WN0 + (jp * 2 + ((lane >> 4) & 1)) * 8
                                                    + (lane & 7));
                    const uint32_t ch  = cA + ((uint32_t)(lane >> 3) & 1u);
                    ldsm_x4(b[jp * 2][0], b[jp * 2][1],
                            b[jp * 2 + 1][0], b[jp * 2 + 1][1], bT + swz(row, ch));
                }
#pragma unroll
                for (int i = 0; i < 4; i++)
#pragma unroll
                    for (int j = 0; j < 4; j++)
                        mma_16816(acc[i][j], a[i], b[j]);
            }
        }

        // ---- epilogue: fp32 stores, clip rows to [start, hi) ----
        const int rbase = start + WM0 + (lane >> 2);
        const int cbase = n0 + WN0 + (lane & 3) * 2;
#pragma unroll
        for (int i = 0; i < 4; i++) {
            const int ra = rbase + i * 16;
            const int rb = ra + 8;
            const bool wa = (ra < hi);
            const bool wb = (rb < hi);
            float* pa = out + (size_t)ra * N_DIM + cbase;
            float* pb = out + (size_t)rb * N_DIM + cbase;
#pragma unroll
            for (int j = 0; j < 4; j++) {
                if (wa) *reinterpret_cast<float2*>(pa + j * 8) =
                    make_float2(acc[i][j][0], acc[i][j][1]);
                if (wb) *reinterpret_cast<float2*>(pb + j * 8) =
                    make_float2(acc[i][j][2], acc[i][j][3]);
            }
        }
    }

    // ---- replay-safe counter reset by the last GEMM block ----
    __syncthreads();
    if (tid == 0) {
        const unsigned old = atomicAdd(&g_done, 1u);
        if (old == GEMM_BLOCKS - 1u) {
#pragma unroll
            for (int r = 0; r < 1 + G_GRP; r++) g_cnt[r] = 0u;
            g_done = 0u;
            __threadfence();
        }
    }
}

// ---------------- launch ----------------
extern "C" void kernel_launch(void* const* d_in, const int* in_sizes, int n_in,
                              void* d_out, int out_size) {
    const float* x    = (const float*)d_in[0];  // [T, K]
    const float* w    = (const float*)d_in[1];  // [G, N, K]
    const int*   offs = (const int*)d_in[2];    // [G]
    float* out = (float*)d_out;                 // [T, N]

    static bool inited = false;
    if (!inited) {
        cudaFuncSetAttribute(grouped_gemm_hmma,
                             cudaFuncAttributeMaxDynamicSharedMemorySize,
                             SMEM_TOTAL);
        inited = true;
    }

    // conversion: all 296 blocks resident in wave 1; PDL trigger at entry
    convert_fp16<<<CVB, CVT>>>(x, w);

    // GEMM launched with programmatic stream serialization: its blocks begin
    // placing while convert runs; data readiness is enforced by the flags.
    {
        cudaLaunchConfig_t cfg = {};
        cfg.gridDim = dim3(N_DIM / BN, MAX_RT, 1);   // 16 x 72
        cfg.blockDim = dim3(256, 1, 1);
        cfg.dynamicSmemBytes = SMEM_TOTAL;
        cfg.stream = 0;
        cudaLaunchAttribute attr[1];
        attr[0].id = cudaLaunchAttributeProgrammaticStreamSerialization;
        attr[0].val.programmaticStreamSerializationAllowed = 1;
        cfg.attrs = attr;
        cfg.numAttrs = 1;
        cudaLaunchKernelEx(&cfg, grouped_gemm_hmma, offs, out);
    }
}

// round 16
// speedup vs baseline: 1.5626x; 1.5626x over previous
#include <cuda_runtime.h>
#include <cuda_fp16.h>
#include <cstdint>

// ---------------- problem constants ----------------
#define T_TOK 8192
#define G_GRP 8
#define K_DIM 1024
#define N_DIM 2048

// ---------------- scratch (fp16) + sync state ----------------
__device__ __half g_xh[(size_t)T_TOK * K_DIM];            // [T, 1024]  16MB
__device__ __half g_wh[(size_t)G_GRP * N_DIM * K_DIM];    // [G*N, 1024] 32MB
__device__ unsigned g_cnt[1 + G_GRP];                     // x, w0..w7 completion
__device__ unsigned g_done;                               // GEMM blocks finished

// ---------------- PTX helpers (baseline features only) ----------------
__device__ __forceinline__ uint32_t smem_u32(const void* p) {
    uint32_t a;
    asm("{ .reg .u64 t; cvta.to.shared.u64 t, %1; cvt.u32.u64 %0, t; }"
        : "=r"(a) : "l"(p));
    return a;
}
__device__ __forceinline__ void cp16(uint32_t dst, const void* src) {
    asm volatile("cp.async.cg.shared.global [%0], [%1], 16;" :: "r"(dst), "l"(src));
}
#define CP_COMMIT() asm volatile("cp.async.commit_group;" ::: "memory")
#define CP_WAIT1()  asm volatile("cp.async.wait_group 1;" ::: "memory")

__device__ __forceinline__ void ldsm_x4(uint32_t& r0, uint32_t& r1,
                                        uint32_t& r2, uint32_t& r3, uint32_t a) {
    asm volatile("ldmatrix.sync.aligned.m8n8.x4.shared.b16 {%0,%1,%2,%3}, [%4];"
                 : "=r"(r0), "=r"(r1), "=r"(r2), "=r"(r3) : "r"(a));
}
__device__ __forceinline__ void mma_16816(float* c, const uint32_t* a,
                                          const uint32_t* b) {
    asm volatile(
        "mma.sync.aligned.m16n8k16.row.col.f32.f16.f16.f32 "
        "{%0,%1,%2,%3}, {%4,%5,%6,%7}, {%8,%9}, {%0,%1,%2,%3};"
        : "+f"(c[0]), "+f"(c[1]), "+f"(c[2]), "+f"(c[3])
        : "r"(a[0]), "r"(a[1]), "r"(a[2]), "r"(a[3]), "r"(b[0]), "r"(b[1]));
}
__device__ __forceinline__ unsigned ld_acq(const unsigned* p) {
    unsigned v;
    asm volatile("ld.acquire.gpu.u32 %0, [%1];" : "=r"(v) : "l"(p));
    return v;
}
__device__ __forceinline__ void cv8(const float* __restrict__ s,
                                    __half* __restrict__ d) {
    const float4 v0 = *reinterpret_cast<const float4*>(s);
    const float4 v1 = *reinterpret_cast<const float4*>(s + 4);
    union { __half h[8]; uint4 u; } P;
    P.h[0] = __float2half_rn(v0.x); P.h[1] = __float2half_rn(v0.y);
    P.h[2] = __float2half_rn(v0.z); P.h[3] = __float2half_rn(v0.w);
    P.h[4] = __float2half_rn(v1.x); P.h[5] = __float2half_rn(v1.y);
    P.h[6] = __float2half_rn(v1.z); P.h[7] = __float2half_rn(v1.w);
    *reinterpret_cast<uint4*>(d) = P.u;
}

// ---------------- tiling / grid constants ----------------
constexpr int BM = 128, BN = 128, BK = 64;
constexpr int TILE = BM * 128;                    // 16384 bytes
constexpr int STAGE_BYTES = 2 * TILE;             // 32768
constexpr int STAGES = 3;
constexpr int SMEM_TOTAL = STAGES * STAGE_BYTES;  // 98304 -> 2 blocks/SM
constexpr int NITER = K_DIM / BK;                 // 16
constexpr int MAX_RT = T_TOK / BM + G_GRP;        // 72
constexpr int CVB = 296;                          // convert blocks = wave 1
constexpr int CVW = 192;                          // blocks that continue into w
constexpr unsigned GEMM_BLOCKS = 16u * MAX_RT;    // 1152
constexpr int GRID = CVB + (int)GEMM_BLOCKS;      // 1448

__device__ __forceinline__ uint32_t swz(uint32_t row, uint32_t chunk) {
    return row * 128u + ((chunk ^ (row & 7u)) << 4);
}

__global__ __launch_bounds__(256, 2)
void fused_grouped(const float* __restrict__ x, const float* __restrict__ w,
                   const int* __restrict__ offs, float* __restrict__ out)
{
    const int bid = blockIdx.x;
    const int tid = threadIdx.x;

    // ================= convert path (bids 0..295, wave-1 resident) ========
    if (bid < CVB) {
        // region 0: x (all 296 blocks, full chip)
        {
            const size_t NX8 = (size_t)T_TOK * K_DIM / 8;   // 1,048,576 chunks
#pragma unroll 4
            for (size_t i = (size_t)bid * 256 + tid; i < NX8; i += (size_t)CVB * 256)
                cv8(x + i * 8, g_xh + i * 8);
            __threadfence();
            __syncthreads();
            if (tid == 0) atomicAdd(&g_cnt[0], 1u);
        }
        // blocks >= CVW retire now, freeing slots for GEMM blocks
        if (bid < CVW) {
            const size_t NW8 = (size_t)N_DIM * K_DIM / 8;   // 262,144 chunks
#pragma unroll 1
            for (int g = 0; g < G_GRP; g++) {               // sequential: w0 first
                const float* src = w + (size_t)g * N_DIM * K_DIM;
                __half* dst = g_wh + (size_t)g * N_DIM * K_DIM;
#pragma unroll 4
                for (size_t i = (size_t)bid * 256 + tid; i < NW8; i += (size_t)CVW * 256)
                    cv8(src + i * 8, dst + i * 8);
                __threadfence();
                __syncthreads();
                if (tid == 0) atomicAdd(&g_cnt[1 + g], 1u);
            }
        }
        return;
    }

    // ================= GEMM path (bids 296..1447) =========================
    const int t = bid - CVB;
    const int pair = t >> 4;
    const int nt   = t & 15;

    // map pair -> (group, group-aligned row tile)
    int g = -1, start = 0, hi = 0;
    {
        int a = 0;
#pragma unroll
        for (int gg = 0; gg < G_GRP; gg++) {
            const int l = gg ? __ldg(offs + gg - 1) : 0;
            const int h = __ldg(offs + gg);
            const int c = (h - l + BM - 1) >> 7;
            if (pair >= a && pair < a + c) { g = gg; start = l + ((pair - a) << 7); hi = h; }
            a += c;
        }
    }

    if (g >= 0) {
        // gate on (x, w_g) conversion completion
        if (tid == 0) {
            while (ld_acq(&g_cnt[0]) < (unsigned)CVB) __nanosleep(128);
            while (ld_acq(&g_cnt[1 + g]) < (unsigned)CVW) __nanosleep(128);
        }
        __syncthreads();

        const int n0 = nt * BN;

        extern __shared__ __align__(1024) char smem[];
        const uint32_t sb = smem_u32(smem);

        const int wid  = tid >> 5;
        const int lane = tid & 31;
        const int WM0 = (wid >> 2) * 64;
        const int WN0 = (wid & 3) * 32;
        const int c8 = tid & 7;
        const int r0 = tid >> 3;

        const __half* aP[4];
        const __half* bP[4];
#pragma unroll
        for (int j = 0; j < 4; j++) {
            int r = start + r0 + 32 * j;
            if (r > T_TOK - 1) r = T_TOK - 1;
            aP[j] = g_xh + (size_t)r * K_DIM + c8 * 8;
            bP[j] = g_wh + ((size_t)g * N_DIM + n0 + r0 + 32 * j) * K_DIM + c8 * 8;
        }

        auto load_stage = [&](int s) {
            const int kb = s * BK;
            const uint32_t base = sb + (uint32_t)(s % STAGES) * STAGE_BYTES;
#pragma unroll
            for (int j = 0; j < 4; j++) {
                const uint32_t so = swz((uint32_t)r0 + 32u * j, c8);
                cp16(base + so,        aP[j] + kb);
                cp16(base + TILE + so, bP[j] + kb);
            }
        };

        float acc[4][4][4];
#pragma unroll
        for (int i = 0; i < 4; i++)
#pragma unroll
            for (int j = 0; j < 4; j++)
#pragma unroll
                for (int q = 0; q < 4; q++) acc[i][j][q] = 0.0f;

        load_stage(0); CP_COMMIT();
        load_stage(1); CP_COMMIT();

        for (int it = 0; it < NITER; it++) {
            CP_WAIT1();
            __syncthreads();

            if (it + 2 < NITER) load_stage(it + 2);
            CP_COMMIT();

            const uint32_t aT = sb + (uint32_t)(it % STAGES) * STAGE_BYTES;
            const uint32_t bT = aT + TILE;

#pragma unroll
            for (int ks = 0; ks < BK / 16; ks++) {
                const uint32_t cA = 2u * ks;
                uint32_t a[4][4], b[4][2];
#pragma unroll
                for (int i = 0; i < 4; i++) {
                    const uint32_t row = (uint32_t)(WM0 + i * 16 + (lane & 15));
                    const uint32_t ch  = cA + (uint32_t)(lane >> 4);
                    ldsm_x4(a[i][0], a[i][1], a[i][2], a[i][3], aT + swz(row, ch));
                }
#pragma unroll
                for (int jp = 0; jp < 2; jp++) {
                    const uint32_t row = (uint32_t)(WN0 + (jp * 2 + ((lane >> 4) & 1)) * 8
                                                    + (lane & 7));
                    const uint32_t ch  = cA + ((uint32_t)(lane >> 3) & 1u);
                    ldsm_x4(b[jp * 2][0], b[jp * 2][1],
                            b[jp * 2 + 1][0], b[jp * 2 + 1][1], bT + swz(row, ch));
                }
#pragma unroll
                for (int i = 0; i < 4; i++)
#pragma unroll
                    for (int j = 0; j < 4; j++)
                        mma_16816(acc[i][j], a[i], b[j]);
            }
        }

        // epilogue: fp32 stores, clip rows to [start, hi)
        const int rbase = start + WM0 + (lane >> 2);
        const int cbase = n0 + WN0 + (lane & 3) * 2;
#pragma unroll
        for (int i = 0; i < 4; i++) {
            const int ra = rbase + i * 16;
            const int rb = ra + 8;
            const bool wa = (ra < hi);
            const bool wb = (rb < hi);
            float* pa = out + (size_t)ra * N_DIM + cbase;
            float* pb = out + (size_t)rb * N_DIM + cbase;
#pragma unroll
            for (int j = 0; j < 4; j++) {
                if (wa) *reinterpret_cast<float2*>(pa + j * 8) =
                    make_float2(acc[i][j][0], acc[i][j][1]);
                if (wb) *reinterpret_cast<float2*>(pb + j * 8) =
                    make_float2(acc[i][j][2], acc[i][j][3]);
            }
        }
    }

    // replay-safe counter reset: last of the 1152 GEMM blocks clears state.
    __syncthreads();
    if (tid == 0) {
        const unsigned old = atomicAdd(&g_done, 1u);
        if (old == GEMM_BLOCKS - 1u) {
#pragma unroll
            for (int r = 0; r < 1 + G_GRP; r++) g_cnt[r] = 0u;
            g_done = 0u;
            __threadfence();
        }
    }
}

// ---------------- launch ----------------
extern "C" void kernel_launch(void* const* d_in, const int* in_sizes, int n_in,
                              void* d_out, int out_size) {
    const float* x    = (const float*)d_in[0];  // [T, K]
    const float* w    = (const float*)d_in[1];  // [G, N, K]
    const int*   offs = (const int*)d_in[2];    // [G]
    float* out = (float*)d_out;                 // [T, N]

    static bool inited = false;
    if (!inited) {
        cudaFuncSetAttribute(fused_grouped,
                             cudaFuncAttributeMaxDynamicSharedMemorySize,
                             SMEM_TOTAL);
        inited = true;
    }

    fused_grouped<<<GRID, 256, SMEM_TOTAL>>>(x, w, offs, out);
}

// round 17
// speedup vs baseline: 1.6462x; 1.0535x over previous
#include <cuda_runtime.h>
#include <cuda_fp16.h>
#include <cstdint>

// ---------------- problem constants ----------------
#define T_TOK 8192
#define G_GRP 8
#define K_DIM 1024
#define N_DIM 2048

// ---------------- scratch (fp16) + sync state ----------------
__device__ __half g_xh[(size_t)T_TOK * K_DIM];            // [T, 1024]  16MB
__device__ __half g_wh[(size_t)G_GRP * N_DIM * K_DIM];    // [G*N, 1024] 32MB
__device__ unsigned g_cnt[1 + G_GRP];                     // x, w0..w7 completion
__device__ unsigned g_done;                               // GEMM blocks finished

// ---------------- PTX helpers (baseline features only) ----------------
__device__ __forceinline__ uint32_t smem_u32(const void* p) {
    uint32_t a;
    asm("{ .reg .u64 t; cvta.to.shared.u64 t, %1; cvt.u32.u64 %0, t; }"
        : "=r"(a) : "l"(p));
    return a;
}
__device__ __forceinline__ void cp16(uint32_t dst, const void* src) {
    asm volatile("cp.async.cg.shared.global [%0], [%1], 16;" :: "r"(dst), "l"(src));
}
#define CP_COMMIT() asm volatile("cp.async.commit_group;" ::: "memory")
#define CP_WAIT1()  asm volatile("cp.async.wait_group 1;" ::: "memory")

__device__ __forceinline__ void ldsm_x4(uint32_t& r0, uint32_t& r1,
                                        uint32_t& r2, uint32_t& r3, uint32_t a) {
    asm volatile("ldmatrix.sync.aligned.m8n8.x4.shared.b16 {%0,%1,%2,%3}, [%4];"
                 : "=r"(r0), "=r"(r1), "=r"(r2), "=r"(r3) : "r"(a));
}
__device__ __forceinline__ void mma_16816(float* c, const uint32_t* a,
                                          const uint32_t* b) {
    asm volatile(
        "mma.sync.aligned.m16n8k16.row.col.f32.f16.f16.f32 "
        "{%0,%1,%2,%3}, {%4,%5,%6,%7}, {%8,%9}, {%0,%1,%2,%3};"
        : "+f"(c[0]), "+f"(c[1]), "+f"(c[2]), "+f"(c[3])
        : "r"(a[0]), "r"(a[1]), "r"(a[2]), "r"(a[3]), "r"(b[0]), "r"(b[1]));
}
__device__ __forceinline__ unsigned ld_acq(const unsigned* p) {
    unsigned v;
    asm volatile("ld.acquire.gpu.u32 %0, [%1];" : "=r"(v) : "l"(p));
    return v;
}
__device__ __forceinline__ void cv8(const float* __restrict__ s,
                                    __half* __restrict__ d) {
    const float4 v0 = *reinterpret_cast<const float4*>(s);
    const float4 v1 = *reinterpret_cast<const float4*>(s + 4);
    union { __half h[8]; uint4 u; } P;
    P.h[0] = __float2half_rn(v0.x); P.h[1] = __float2half_rn(v0.y);
    P.h[2] = __float2half_rn(v0.z); P.h[3] = __float2half_rn(v0.w);
    P.h[4] = __float2half_rn(v1.x); P.h[5] = __float2half_rn(v1.y);
    P.h[6] = __float2half_rn(v1.z); P.h[7] = __float2half_rn(v1.w);
    *reinterpret_cast<uint4*>(d) = P.u;
}

// ---------------- tiling / grid constants ----------------
constexpr int BM = 128, BN = 128, BK = 64;
constexpr int TILE = BM * 128;                    // 16384 bytes
constexpr int STAGE_BYTES = 2 * TILE;             // 32768
constexpr int STAGES = 3;
constexpr int SMEM_TOTAL = STAGES * STAGE_BYTES;  // 98304 -> 2 blocks/SM
constexpr int NITER = K_DIM / BK;                 // 16
constexpr int MAX_RT = T_TOK / BM + G_GRP;        // 72
constexpr int CVB = 296;                          // convert blocks = wave 1
constexpr int CVW = 128;                          // blocks that continue into w
constexpr unsigned GEMM_BLOCKS = 16u * MAX_RT;    // 1152
constexpr int GRID = CVB + (int)GEMM_BLOCKS;      // 1448

__device__ __forceinline__ uint32_t swz(uint32_t row, uint32_t chunk) {
    return row * 128u + ((chunk ^ (row & 7u)) << 4);
}

__global__ __launch_bounds__(256, 2)
void fused_grouped(const float* __restrict__ x, const float* __restrict__ w,
                   const int* __restrict__ offs, float* __restrict__ out)
{
    const int bid = blockIdx.x;
    const int tid = threadIdx.x;

    // ================= convert path (bids 0..295, wave-1 resident) ========
    if (bid < CVB) {
        // region 0: x (all 296 blocks, full chip)
        {
            const size_t NX8 = (size_t)T_TOK * K_DIM / 8;   // 1,048,576 chunks
#pragma unroll 4
            for (size_t i = (size_t)bid * 256 + tid; i < NX8; i += (size_t)CVB * 256)
                cv8(x + i * 8, g_xh + i * 8);
            __threadfence();
            __syncthreads();
            if (tid == 0) atomicAdd(&g_cnt[0], 1u);
        }
        // blocks >= CVW retire now, freeing slots for GEMM blocks
        if (bid < CVW) {
            const size_t NW8 = (size_t)N_DIM * K_DIM / 8;   // 262,144 chunks
#pragma unroll 1
            for (int g = 0; g < G_GRP; g++) {               // sequential: w0 first
                const float* src = w + (size_t)g * N_DIM * K_DIM;
                __half* dst = g_wh + (size_t)g * N_DIM * K_DIM;
#pragma unroll 4
                for (size_t i = (size_t)bid * 256 + tid; i < NW8; i += (size_t)CVW * 256)
                    cv8(src + i * 8, dst + i * 8);
                __threadfence();
                __syncthreads();
                if (tid == 0) atomicAdd(&g_cnt[1 + g], 1u);
            }
        }
        return;
    }

    // ================= GEMM path (bids 296..1447) =========================
    const int t = bid - CVB;
    const int pair = t >> 4;
    const int nt   = t & 15;

    // map pair -> (group, group-aligned row tile)
    int g = -1, start = 0, hi = 0;
    {
        int a = 0;
#pragma unroll
        for (int gg = 0; gg < G_GRP; gg++) {
            const int l = gg ? __ldg(offs + gg - 1) : 0;
            const int h = __ldg(offs + gg);
            const int c = (h - l + BM - 1) >> 7;
            if (pair >= a && pair < a + c) { g = gg; start = l + ((pair - a) << 7); hi = h; }
            a += c;
        }
    }

    if (g >= 0) {
        // gate on (x, w_g) conversion completion
        if (tid == 0) {
            while (ld_acq(&g_cnt[0]) < (unsigned)CVB) __nanosleep(128);
            while (ld_acq(&g_cnt[1 + g]) < (unsigned)CVW) __nanosleep(128);
        }
        __syncthreads();

        const int n0 = nt * BN;

        extern __shared__ __align__(1024) char smem[];
        const uint32_t sb = smem_u32(smem);

        const int wid  = tid >> 5;
        const int lane = tid & 31;
        const int WM0 = (wid >> 2) * 64;
        const int WN0 = (wid & 3) * 32;
        const int c8 = tid & 7;
        const int r0 = tid >> 3;

        const __half* aP[4];
        const __half* bP[4];
#pragma unroll
        for (int j = 0; j < 4; j++) {
            int r = start + r0 + 32 * j;
            if (r > T_TOK - 1) r = T_TOK - 1;
            aP[j] = g_xh + (size_t)r * K_DIM + c8 * 8;
            bP[j] = g_wh + ((size_t)g * N_DIM + n0 + r0 + 32 * j) * K_DIM + c8 * 8;
        }

        auto load_stage = [&](int s) {
            const int kb = s * BK;
            const uint32_t base = sb + (uint32_t)(s % STAGES) * STAGE_BYTES;
#pragma unroll
            for (int j = 0; j < 4; j++) {
                const uint32_t so = swz((uint32_t)r0 + 32u * j, c8);
                cp16(base + so,        aP[j] + kb);
                cp16(base + TILE + so, bP[j] + kb);
            }
        };

        float acc[4][4][4];
#pragma unroll
        for (int i = 0; i < 4; i++)
#pragma unroll
            for (int j = 0; j < 4; j++)
#pragma unroll
                for (int q = 0; q < 4; q++) acc[i][j][q] = 0.0f;

        load_stage(0); CP_COMMIT();
        load_stage(1); CP_COMMIT();

        for (int it = 0; it < NITER; it++) {
            CP_WAIT1();
            __syncthreads();

            if (it + 2 < NITER) load_stage(it + 2);
            CP_COMMIT();

            const uint32_t aT = sb + (uint32_t)(it % STAGES) * STAGE_BYTES;
            const uint32_t bT = aT + TILE;

#pragma unroll
            for (int ks = 0; ks < BK / 16; ks++) {
                const uint32_t cA = 2u * ks;
                uint32_t a[4][4], b[4][2];
#pragma unroll
                for (int i = 0; i < 4; i++) {
                    const uint32_t row = (uint32_t)(WM0 + i * 16 + (lane & 15));
                    const uint32_t ch  = cA + (uint32_t)(lane >> 4);
                    ldsm_x4(a[i][0], a[i][1], a[i][2], a[i][3], aT + swz(row, ch));
                }
#pragma unroll
                for (int jp = 0; jp < 2; jp++) {
                    const uint32_t row = (uint32_t)(WN0 + (jp * 2 + ((lane >> 4) & 1)) * 8
                                                    + (lane & 7));
                    const uint32_t ch  = cA + ((uint32_t)(lane >> 3) & 1u);
                    ldsm_x4(b[jp * 2][0], b[jp * 2][1],
                            b[jp * 2 + 1][0], b[jp * 2 + 1][1], bT + swz(row, ch));
                }
#pragma unroll
                for (int i = 0; i < 4; i++)
#pragma unroll
                    for (int j = 0; j < 4; j++)
                        mma_16816(acc[i][j], a[i], b[j]);
            }
        }

        // epilogue: fp32 stores, clip rows to [start, hi)
        const int rbase = start + WM0 + (lane >> 2);
        const int cbase = n0 + WN0 + (lane & 3) * 2;
#pragma unroll
        for (int i = 0; i < 4; i++) {
            const int ra = rbase + i * 16;
            const int rb = ra + 8;
            const bool wa = (ra < hi);
            const bool wb = (rb < hi);
            float* pa = out + (size_t)ra * N_DIM + cbase;
            float* pb = out + (size_t)rb * N_DIM + cbase;
#pragma unroll
            for (int j = 0; j < 4; j++) {
                if (wa) *reinterpret_cast<float2*>(pa + j * 8) =
                    make_float2(acc[i][j][0], acc[i][j][1]);
                if (wb) *reinterpret_cast<float2*>(pb + j * 8) =
                    make_float2(acc[i][j][2], acc[i][j][3]);
            }
        }
    }

    // replay-safe counter reset: last of the 1152 GEMM blocks clears state.
    __syncthreads();
    if (tid == 0) {
        const unsigned old = atomicAdd(&g_done, 1u);
        if (old == GEMM_BLOCKS - 1u) {
#pragma unroll
            for (int r = 0; r < 1 + G_GRP; r++) g_cnt[r] = 0u;
            g_done = 0u;
            __threadfence();
        }
    }
}

// ---------------- launch ----------------
extern "C" void kernel_launch(void* const* d_in, const int* in_sizes, int n_in,
                              void* d_out, int out_size) {
    const float* x    = (const float*)d_in[0];  // [T, K]
    const float* w    = (const float*)d_in[1];  // [G, N, K]
    const int*   offs = (const int*)d_in[2];    // [G]
    float* out = (float*)d_out;                 // [T, N]

    static bool inited = false;
    if (!inited) {
        cudaFuncSetAttribute(fused_grouped,
                             cudaFuncAttributeMaxDynamicSharedMemorySize,
                             SMEM_TOTAL);
        inited = true;
    }

    fused_grouped<<<GRID, 256, SMEM_TOTAL>>>(x, w, offs, out);
}